// round 1
// baseline (speedup 1.0000x reference)
#include <cuda_runtime.h>
#include <cuda_bf16.h>
#include <math.h>

// Problem constants
#define BB   32
#define TT   64
#define DD   63
#define EE   256
#define HH   1024
#define H3   3072
#define VV   16000

// ---------------------------------------------------------------------------
// Scratch (device globals; no runtime allocation allowed)
// ---------------------------------------------------------------------------
__device__ float g_xz_enc[BB * TT * H3];   // [B,T,3H]
__device__ float g_xz_dec[BB * DD * H3];   // [B,D,3H]
__device__ float g_enc_out[BB * TT * HH];  // [B,T,H]
__device__ float g_dec_out[BB * DD * HH];  // [B,D,H]
__device__ float g_w1e[BB * TT * HH];      // [B,T,H]
__device__ float g_w2d[BB * DD * HH];      // [B,D,H]
__device__ float g_attn[BB * DD * TT];     // [B,D,T]
__device__ float g_av[BB * DD * 2 * HH];   // [B,D,2H]

__device__ __forceinline__ float sigmoidf_(float x) { return 1.0f / (1.0f + expf(-x)); }

__device__ __forceinline__ float fast_tanh(float x) {
    float y;
    asm("tanh.approx.f32 %0, %1;" : "=f"(y) : "f"(x));
    return y;
}

// ---------------------------------------------------------------------------
// Generic tiled SGEMM: C[M,N] = gatherA(M,K) @ Bm[K,N] (+ bias[n])
// BM=BN=64, BK=16, 256 threads, 4x4 microtile. N % 64 == 0, K % 16 == 0.
// If ids != nullptr: A row m comes from emb[ids[(m/seqlen)*64 + m%seqlen], :K].
// ---------------------------------------------------------------------------
__global__ void sgemm64(const float* __restrict__ A,
                        const float* __restrict__ Bm,
                        const float* __restrict__ bias,
                        float* __restrict__ C,
                        int M, int N, int K,
                        const int* __restrict__ ids, int seqlen,
                        const float* __restrict__ emb)
{
    __shared__ float As[16][65];
    __shared__ float Bs[16][64];

    const int bm = blockIdx.y * 64;
    const int bn = blockIdx.x * 64;
    const int t  = threadIdx.x;           // 0..255
    const int tx = t & 15;                // N dir
    const int ty = t >> 4;                // M dir

    float acc[4][4];
#pragma unroll
    for (int i = 0; i < 4; i++)
#pragma unroll
        for (int j = 0; j < 4; j++) acc[i][j] = 0.0f;

    for (int k0 = 0; k0 < K; k0 += 16) {
        // Stage A tile (64 rows x 16 k), coalesced 16 lanes per row
#pragma unroll
        for (int i = 0; i < 4; i++) {
            int flat = t + i * 256;
            int ml = flat >> 4;
            int kk = flat & 15;
            int m = bm + ml;
            float v = 0.0f;
            if (m < M) {
                const float* arow;
                if (ids) {
                    int b  = m / seqlen;
                    int tt = m - b * seqlen;
                    arow = emb + (size_t)ids[b * 64 + tt] * K;
                } else {
                    arow = A + (size_t)m * K;
                }
                v = arow[k0 + kk];
            }
            As[kk][ml] = v;
        }
        // Stage B tile (16 k x 64 n), coalesced
#pragma unroll
        for (int i = 0; i < 4; i++) {
            int flat = t + i * 256;
            int kk = flat >> 6;
            int nl = flat & 63;
            Bs[kk][nl] = Bm[(size_t)(k0 + kk) * N + bn + nl];
        }
        __syncthreads();

#pragma unroll
        for (int kk = 0; kk < 16; kk++) {
            float a[4], bv[4];
#pragma unroll
            for (int i = 0; i < 4; i++) a[i] = As[kk][ty * 4 + i];
#pragma unroll
            for (int j = 0; j < 4; j++) bv[j] = Bs[kk][tx * 4 + j];
#pragma unroll
            for (int i = 0; i < 4; i++)
#pragma unroll
                for (int j = 0; j < 4; j++) acc[i][j] += a[i] * bv[j];
        }
        __syncthreads();
    }

#pragma unroll
    for (int i = 0; i < 4; i++) {
        int m = bm + ty * 4 + i;
        if (m >= M) break;
        float* crow = C + (size_t)m * N + bn;
#pragma unroll
        for (int j = 0; j < 4; j++) {
            int n = tx * 4 + j;
            float v = acc[i][j];
            if (bias) v += bias[bn + n];
            crow[n] = v;
        }
    }
}

// ---------------------------------------------------------------------------
// One GRU time step (fused hz = h@Wh GEMM + gates).
// grid = 128 blocks (8 h-columns each), 256 threads.
// hprev == nullptr means h = 0 (first encoder step).
// ---------------------------------------------------------------------------
__global__ void gru_step_kernel(const float* __restrict__ xz_base, int xz_rs,
                                const float* __restrict__ hprev, int h_rs,
                                const float* __restrict__ Wh,
                                float* __restrict__ hout, int out_rs)
{
    __shared__ float h_s[64][33];   // [k][b]
    __shared__ float w_s[64][24];   // [k][gate*8 + c]

    const int t  = threadIdx.x;     // 0..255
    const int c0 = blockIdx.x * 8;
    const int b  = t & 31;
    const int c  = t >> 5;          // 0..7

    float a0 = 0.0f, a1 = 0.0f, a2 = 0.0f;

    for (int kt = 0; kt < HH; kt += 64) {
        // Stage h tile: thread loads 8 consecutive k for row b
        {
            int lb = t & 31;
            int kg = t >> 5;                 // 0..7
            int kbase = kt + kg * 8;
            if (hprev) {
                float4 v0 = *(const float4*)(hprev + (size_t)lb * h_rs + kbase);
                float4 v1 = *(const float4*)(hprev + (size_t)lb * h_rs + kbase + 4);
                h_s[kg * 8 + 0][lb] = v0.x; h_s[kg * 8 + 1][lb] = v0.y;
                h_s[kg * 8 + 2][lb] = v0.z; h_s[kg * 8 + 3][lb] = v0.w;
                h_s[kg * 8 + 4][lb] = v1.x; h_s[kg * 8 + 5][lb] = v1.y;
                h_s[kg * 8 + 6][lb] = v1.z; h_s[kg * 8 + 7][lb] = v1.w;
            } else {
#pragma unroll
                for (int i = 0; i < 8; i++) h_s[kg * 8 + i][lb] = 0.0f;
            }
        }
        // Stage Wh tile: 64 k x 24 cols (3 gates x 8 cols)
#pragma unroll
        for (int j = 0; j < 6; j++) {
            int flat = t + j * 256;
            int kk  = flat / 24;
            int c24 = flat - kk * 24;
            int gate = c24 >> 3;
            int cc   = c24 & 7;
            w_s[kk][c24] = Wh[(size_t)(kt + kk) * H3 + gate * HH + c0 + cc];
        }
        __syncthreads();

#pragma unroll
        for (int kk = 0; kk < 64; kk++) {
            float hv = h_s[kk][b];
            a0 += hv * w_s[kk][c];
            a1 += hv * w_s[kk][8 + c];
            a2 += hv * w_s[kk][16 + c];
        }
        __syncthreads();
    }

    const int col = c0 + c;
    const float* xzp = xz_base + (size_t)b * xz_rs;
    float z  = sigmoidf_(xzp[col] + a0);
    float r  = sigmoidf_(xzp[HH + col] + a1);
    float hh = tanhf(xzp[2 * HH + col] + r * a2);
    float hp = hprev ? hprev[(size_t)b * h_rs + col] : 0.0f;
    hout[(size_t)b * out_rs + col] = z * hp + (1.0f - z) * hh;
}

// ---------------------------------------------------------------------------
// Attention scores + softmax over encoder positions.
// One block per (b,d). scores[e] = Vb + sum_k tanh(w1e[b,e,k]+w2d[b,d,k])*Vw[k]
// ---------------------------------------------------------------------------
__global__ void attn_scores_kernel(const float* __restrict__ w1e,
                                   const float* __restrict__ w2d,
                                   const float* __restrict__ Vw,
                                   const float* __restrict__ Vb,
                                   float* __restrict__ attn)
{
    __shared__ float w2s[HH];
    __shared__ float vws[HH];
    __shared__ float ss[TT];

    const int bd = blockIdx.x;          // b*63 + d
    const int b  = bd / DD;
    const int t  = threadIdx.x;

    for (int k = t; k < HH; k += 256) {
        w2s[k] = w2d[(size_t)bd * HH + k];
        vws[k] = Vw[k];
    }
    __syncthreads();

    const int wid = t >> 5, lane = t & 31;
    for (int e = wid; e < TT; e += 8) {
        const float* w1p = w1e + ((size_t)b * TT + e) * HH;
        float acc = 0.0f;
        for (int k = lane; k < HH; k += 32)
            acc += fast_tanh(w1p[k] + w2s[k]) * vws[k];
#pragma unroll
        for (int o = 16; o; o >>= 1) acc += __shfl_xor_sync(0xffffffffu, acc, o);
        if (lane == 0) ss[e] = acc + Vb[0];
    }
    __syncthreads();

    if (t < 32) {
        float v0 = ss[t], v1 = ss[t + 32];
        float m = fmaxf(v0, v1);
#pragma unroll
        for (int o = 16; o; o >>= 1) m = fmaxf(m, __shfl_xor_sync(0xffffffffu, m, o));
        float e0 = expf(v0 - m), e1 = expf(v1 - m);
        float s = e0 + e1;
#pragma unroll
        for (int o = 16; o; o >>= 1) s += __shfl_xor_sync(0xffffffffu, s, o);
        float inv = 1.0f / s;
        attn[(size_t)bd * TT + t]      = e0 * inv;
        attn[(size_t)bd * TT + t + 32] = e1 * inv;
    }
}

// ---------------------------------------------------------------------------
// context = attn @ enc_out, attention_vector = tanh([context, dec_out]).
// One block per (b,d), 256 threads, 4 h each (float4 path).
// ---------------------------------------------------------------------------
__global__ void context_av_kernel(const float* __restrict__ attn,
                                  const float* __restrict__ enc_out,
                                  const float* __restrict__ dec_out,
                                  float* __restrict__ av)
{
    __shared__ float as[TT];
    const int bd = blockIdx.x;
    const int b  = bd / DD;
    const int t  = threadIdx.x;

    if (t < TT) as[t] = attn[(size_t)bd * TT + t];
    __syncthreads();

    const int h0 = t * 4;
    float ax = 0, ay = 0, az = 0, aw = 0;
#pragma unroll 4
    for (int e = 0; e < TT; e++) {
        float a = as[e];
        float4 v = *(const float4*)(enc_out + ((size_t)b * TT + e) * HH + h0);
        ax += a * v.x; ay += a * v.y; az += a * v.z; aw += a * v.w;
    }
    float* avp = av + (size_t)bd * (2 * HH);
    avp[h0 + 0] = tanhf(ax);
    avp[h0 + 1] = tanhf(ay);
    avp[h0 + 2] = tanhf(az);
    avp[h0 + 3] = tanhf(aw);

    float4 dv = *(const float4*)(dec_out + (size_t)bd * HH + h0);
    avp[HH + h0 + 0] = tanhf(dv.x);
    avp[HH + h0 + 1] = tanhf(dv.y);
    avp[HH + h0 + 2] = tanhf(dv.z);
    avp[HH + h0 + 3] = tanhf(dv.w);
}

// ---------------------------------------------------------------------------
// Host launcher
// ---------------------------------------------------------------------------
extern "C" void kernel_launch(void* const* d_in, const int* in_sizes, int n_in,
                              void* d_out, int out_size)
{
    const int*   input_ids  = (const int*)  d_in[0];
    const int*   target_ids = (const int*)  d_in[1];
    const float* emb_enc    = (const float*)d_in[2];
    const float* emb_dec    = (const float*)d_in[3];
    const float* enc_Wx     = (const float*)d_in[4];
    const float* enc_Wh     = (const float*)d_in[5];
    const float* enc_b      = (const float*)d_in[6];
    const float* dec_Wx     = (const float*)d_in[7];
    const float* dec_Wh     = (const float*)d_in[8];
    const float* dec_b      = (const float*)d_in[9];
    const float* W1         = (const float*)d_in[10];
    const float* W2         = (const float*)d_in[11];
    const float* V_w        = (const float*)d_in[12];
    const float* V_b        = (const float*)d_in[13];
    const float* Wp         = (const float*)d_in[14];
    const float* bp         = (const float*)d_in[15];
    float* out = (float*)d_out;

    float *xz_enc, *xz_dec, *enc_out, *dec_out, *w1e, *w2d, *attn, *av;
    cudaGetSymbolAddress((void**)&xz_enc,  g_xz_enc);
    cudaGetSymbolAddress((void**)&xz_dec,  g_xz_dec);
    cudaGetSymbolAddress((void**)&enc_out, g_enc_out);
    cudaGetSymbolAddress((void**)&dec_out, g_dec_out);
    cudaGetSymbolAddress((void**)&w1e,     g_w1e);
    cudaGetSymbolAddress((void**)&w2d,     g_w2d);
    cudaGetSymbolAddress((void**)&attn,    g_attn);
    cudaGetSymbolAddress((void**)&av,      g_av);

    // 1) xz = emb[ids] @ Wx + b  (encoder: M=2048, decoder: M=2016), N=3072, K=256
    {
        dim3 grid(H3 / 64, (BB * TT + 63) / 64);
        sgemm64<<<grid, 256>>>(nullptr, enc_Wx, enc_b, xz_enc,
                               BB * TT, H3, EE, input_ids, TT, emb_enc);
    }
    {
        dim3 grid(H3 / 64, (BB * DD + 63) / 64);
        sgemm64<<<grid, 256>>>(nullptr, dec_Wx, dec_b, xz_dec,
                               BB * DD, H3, EE, target_ids, DD, emb_dec);
    }

    // 2) Encoder GRU: 64 sequential steps. h_t written into enc_out[:, t, :].
    for (int t = 0; t < TT; t++) {
        const float* hprev = (t == 0) ? nullptr : (enc_out + (size_t)(t - 1) * HH);
        gru_step_kernel<<<128, 256>>>(xz_enc + (size_t)t * H3, TT * H3,
                                      hprev, TT * HH,
                                      enc_Wh,
                                      enc_out + (size_t)t * HH, TT * HH);
    }

    // 3) Decoder GRU: 63 steps, h0 = enc_out[:, 63, :]
    for (int t = 0; t < DD; t++) {
        const float* hprev;
        int h_rs;
        if (t == 0) { hprev = enc_out + (size_t)(TT - 1) * HH; h_rs = TT * HH; }
        else        { hprev = dec_out + (size_t)(t - 1) * HH;  h_rs = DD * HH; }
        gru_step_kernel<<<128, 256>>>(xz_dec + (size_t)t * H3, DD * H3,
                                      hprev, h_rs,
                                      dec_Wh,
                                      dec_out + (size_t)t * HH, DD * HH);
    }

    // 4) w1e = enc_out @ W1, w2d = dec_out @ W2
    {
        dim3 grid(HH / 64, (BB * TT + 63) / 64);
        sgemm64<<<grid, 256>>>(enc_out, W1, nullptr, w1e,
                               BB * TT, HH, HH, nullptr, 0, nullptr);
    }
    {
        dim3 grid(HH / 64, (BB * DD + 63) / 64);
        sgemm64<<<grid, 256>>>(dec_out, W2, nullptr, w2d,
                               BB * DD, HH, HH, nullptr, 0, nullptr);
    }

    // 5) attention scores + softmax
    attn_scores_kernel<<<BB * DD, 256>>>(w1e, w2d, V_w, V_b, attn);

    // 6) context + attention vector
    context_av_kernel<<<BB * DD, 256>>>(attn, enc_out, dec_out, av);

    // 7) logits = av @ Wp + bp  (M=2016, N=16000, K=2048)
    {
        dim3 grid(VV / 64, (BB * DD + 63) / 64);
        sgemm64<<<grid, 256>>>(av, Wp, bp, out,
                               BB * DD, VV, 2 * HH, nullptr, 0, nullptr);
    }
    (void)in_sizes; (void)n_in; (void)out_size;
}

// round 5
// speedup vs baseline: 1.6754x; 1.6754x over previous
#include <cuda_runtime.h>
#include <cuda_bf16.h>
#include <math.h>

// Problem constants
#define BB   32
#define TT   64
#define DD   63
#define EE   256
#define HH   1024
#define H3   3072
#define VV   16000

// ---------------------------------------------------------------------------
// Scratch (device globals; no runtime allocation allowed)
// ---------------------------------------------------------------------------
__device__ float g_xz_enc[BB * TT * H3];   // [B,T,3H]
__device__ float g_xz_dec[BB * DD * H3];   // [B,D,3H]
__device__ float g_enc_out[BB * TT * HH];  // [B,T,H]
__device__ float g_dec_out[BB * DD * HH];  // [B,D,H]
__device__ float g_w1e[BB * TT * HH];      // [B,T,H]
__device__ float g_w2d[BB * DD * HH];      // [B,D,H]
__device__ float g_attn[BB * DD * TT];     // [B,D,T]
__device__ float g_av[BB * DD * 2 * HH];   // [B,D,2H]

__device__ __forceinline__ float sigmoidf_(float x) { return 1.0f / (1.0f + expf(-x)); }

__device__ __forceinline__ float fast_tanh(float x) {
    float y;
    asm("tanh.approx.f32 %0, %1;" : "=f"(y) : "f"(x));
    return y;
}

// ---------------------------------------------------------------------------
// Tiled SGEMM v2: C[M,N] = gatherA(M,K) @ Bm[K,N] (+ bias[n])
// BM=128, BN=64, BK=16, 256 threads, 8x4 microtile, float4 smem traffic,
// software-pipelined global staging. N % 64 == 0, K % 16 == 0.
// If ids != nullptr: A row m comes from emb[ids[(m/seqlen)*64 + m%seqlen], :K].
// ---------------------------------------------------------------------------
__global__ __launch_bounds__(256) void sgemm128(
        const float* __restrict__ A,
        const float* __restrict__ Bm,
        const float* __restrict__ bias,
        float* __restrict__ C,
        int M, int N, int K,
        const int* __restrict__ ids, int seqlen,
        const float* __restrict__ emb)
{
    __shared__ float As[16][132];   // [k][m], 132-pad keeps rows 16B-aligned
    __shared__ float Bs[16][64];    // [k][n]

    const int bm = blockIdx.y * 128;
    const int bn = blockIdx.x * 64;
    const int t  = threadIdx.x;     // 0..255
    const int tx = t & 15;          // N dir (4 cols)
    const int ty = t >> 4;          // M dir (8 rows)

    // staging maps
    const int a_ml0 = (t) >> 2;            // i=0
    const int a_q0  = (t) & 3;
    const int a_ml1 = (t + 256) >> 2;      // i=1
    const int a_q1  = (t + 256) & 3;
    const int b_kk  = t >> 4;
    const int b_n4  = t & 15;

    float acc[8][4];
#pragma unroll
    for (int i = 0; i < 8; i++)
#pragma unroll
        for (int j = 0; j < 4; j++) acc[i][j] = 0.0f;

    // resolve A row pointers for the two staged rows (gather or direct)
    const float* arow0 = nullptr;
    const float* arow1 = nullptr;
    {
        int m0 = bm + a_ml0, m1 = bm + a_ml1;
        if (m0 < M) {
            if (ids) { int b = m0 / seqlen, tt2 = m0 - b * seqlen;
                       arow0 = emb + (size_t)ids[b * 64 + tt2] * K; }
            else       arow0 = A + (size_t)m0 * K;
        }
        if (m1 < M) {
            if (ids) { int b = m1 / seqlen, tt2 = m1 - b * seqlen;
                       arow1 = emb + (size_t)ids[b * 64 + tt2] * K; }
            else       arow1 = A + (size_t)m1 * K;
        }
    }

    const int ntiles = K >> 4;
    float4 ra0, ra1, rb;

    // prologue: load tile 0
    ra0 = arow0 ? *(const float4*)(arow0 + a_q0 * 4) : make_float4(0.f,0.f,0.f,0.f);
    ra1 = arow1 ? *(const float4*)(arow1 + a_q1 * 4) : make_float4(0.f,0.f,0.f,0.f);
    rb  = *(const float4*)(Bm + (size_t)b_kk * N + bn + b_n4 * 4);
    // store tile 0 to smem
    As[a_q0*4+0][a_ml0] = ra0.x; As[a_q0*4+1][a_ml0] = ra0.y;
    As[a_q0*4+2][a_ml0] = ra0.z; As[a_q0*4+3][a_ml0] = ra0.w;
    As[a_q1*4+0][a_ml1] = ra1.x; As[a_q1*4+1][a_ml1] = ra1.y;
    As[a_q1*4+2][a_ml1] = ra1.z; As[a_q1*4+3][a_ml1] = ra1.w;
    *(float4*)&Bs[b_kk][b_n4*4] = rb;

    for (int tile = 0; tile < ntiles; tile++) {
        __syncthreads();
        // prefetch next tile into registers
        if (tile + 1 < ntiles) {
            int k0 = (tile + 1) << 4;
            ra0 = arow0 ? *(const float4*)(arow0 + k0 + a_q0 * 4) : make_float4(0.f,0.f,0.f,0.f);
            ra1 = arow1 ? *(const float4*)(arow1 + k0 + a_q1 * 4) : make_float4(0.f,0.f,0.f,0.f);
            rb  = *(const float4*)(Bm + (size_t)(k0 + b_kk) * N + bn + b_n4 * 4);
        }
        // compute current tile
#pragma unroll
        for (int kk = 0; kk < 16; kk++) {
            float4 a0 = *(const float4*)&As[kk][ty * 8];
            float4 a1 = *(const float4*)&As[kk][ty * 8 + 4];
            float4 b0 = *(const float4*)&Bs[kk][tx * 4];
            acc[0][0] += a0.x*b0.x; acc[0][1] += a0.x*b0.y; acc[0][2] += a0.x*b0.z; acc[0][3] += a0.x*b0.w;
            acc[1][0] += a0.y*b0.x; acc[1][1] += a0.y*b0.y; acc[1][2] += a0.y*b0.z; acc[1][3] += a0.y*b0.w;
            acc[2][0] += a0.z*b0.x; acc[2][1] += a0.z*b0.y; acc[2][2] += a0.z*b0.z; acc[2][3] += a0.z*b0.w;
            acc[3][0] += a0.w*b0.x; acc[3][1] += a0.w*b0.y; acc[3][2] += a0.w*b0.z; acc[3][3] += a0.w*b0.w;
            acc[4][0] += a1.x*b0.x; acc[4][1] += a1.x*b0.y; acc[4][2] += a1.x*b0.z; acc[4][3] += a1.x*b0.w;
            acc[5][0] += a1.y*b0.x; acc[5][1] += a1.y*b0.y; acc[5][2] += a1.y*b0.z; acc[5][3] += a1.y*b0.w;
            acc[6][0] += a1.z*b0.x; acc[6][1] += a1.z*b0.y; acc[6][2] += a1.z*b0.z; acc[6][3] += a1.z*b0.w;
            acc[7][0] += a1.w*b0.x; acc[7][1] += a1.w*b0.y; acc[7][2] += a1.w*b0.z; acc[7][3] += a1.w*b0.w;
        }
        __syncthreads();
        if (tile + 1 < ntiles) {
            As[a_q0*4+0][a_ml0] = ra0.x; As[a_q0*4+1][a_ml0] = ra0.y;
            As[a_q0*4+2][a_ml0] = ra0.z; As[a_q0*4+3][a_ml0] = ra0.w;
            As[a_q1*4+0][a_ml1] = ra1.x; As[a_q1*4+1][a_ml1] = ra1.y;
            As[a_q1*4+2][a_ml1] = ra1.z; As[a_q1*4+3][a_ml1] = ra1.w;
            *(float4*)&Bs[b_kk][b_n4*4] = rb;
        }
    }

    // epilogue
    float4 bv = make_float4(0.f,0.f,0.f,0.f);
    if (bias) bv = *(const float4*)(bias + bn + tx * 4);
#pragma unroll
    for (int i = 0; i < 8; i++) {
        int m = bm + ty * 8 + i;
        if (m < M) {
            float4 o;
            o.x = acc[i][0] + bv.x; o.y = acc[i][1] + bv.y;
            o.z = acc[i][2] + bv.z; o.w = acc[i][3] + bv.w;
            *(float4*)(C + (size_t)m * N + bn + tx * 4) = o;
        }
    }
}

// ---------------------------------------------------------------------------
// One GRU time step v2 (fused hz = h@Wh GEMM + gates).
// grid = 128 blocks (8 h-columns each = 24 gate-cols), 256 threads.
// Vectorized LDS.128, software-pipelined staging. hprev==nullptr -> h=0.
// ---------------------------------------------------------------------------
__global__ __launch_bounds__(256) void gru_step_kernel(
        const float* __restrict__ xz_base, int xz_rs,
        const float* __restrict__ hprev, int h_rs,
        const float* __restrict__ Wh,
        float* __restrict__ hout, int out_rs)
{
    __shared__ float h_s[32][68];   // [b][k], 68-pad: 16B-aligned, conflict-free
    __shared__ float w_s[24][68];   // [gate*8+c][k]

    const int t  = threadIdx.x;     // 0..255
    const int c0 = blockIdx.x * 8;
    const int b  = t & 31;
    const int c  = t >> 5;          // 0..7

    // h staging map: 512 float4 over [32][16], 2 per thread
    const int h_row0 = t >> 4;            // i=0: rows 0..15
    const int h_q0   = t & 15;
    const int h_row1 = (t + 256) >> 4;    // i=1: rows 16..31
    const int h_q1   = (t + 256) & 15;

    float a0 = 0.0f, a1 = 0.0f, a2 = 0.0f;

    float4 rh0, rh1;
    float  rw[6];
    int    w_kk[6], w_c24[6];
#pragma unroll
    for (int i = 0; i < 6; i++) {
        int flat = t + i * 256;           // 0..1535
        w_kk[i]  = flat / 24;
        w_c24[i] = flat - w_kk[i] * 24;
    }

    // prologue: load tile 0
    if (hprev) {
        rh0 = *(const float4*)(hprev + (size_t)h_row0 * h_rs + h_q0 * 4);
        rh1 = *(const float4*)(hprev + (size_t)h_row1 * h_rs + h_q1 * 4);
    } else {
        rh0 = make_float4(0.f,0.f,0.f,0.f);
        rh1 = rh0;
    }
#pragma unroll
    for (int i = 0; i < 6; i++) {
        int gate = w_c24[i] >> 3, cc = w_c24[i] & 7;
        rw[i] = Wh[(size_t)w_kk[i] * H3 + gate * HH + c0 + cc];
    }
    *(float4*)&h_s[h_row0][h_q0 * 4] = rh0;
    *(float4*)&h_s[h_row1][h_q1 * 4] = rh1;
#pragma unroll
    for (int i = 0; i < 6; i++) w_s[w_c24[i]][w_kk[i]] = rw[i];

    for (int tile = 0; tile < 16; tile++) {
        __syncthreads();
        // prefetch next tile
        if (tile + 1 < 16) {
            int k0 = (tile + 1) * 64;
            if (hprev) {
                rh0 = *(const float4*)(hprev + (size_t)h_row0 * h_rs + k0 + h_q0 * 4);
                rh1 = *(const float4*)(hprev + (size_t)h_row1 * h_rs + k0 + h_q1 * 4);
            }
#pragma unroll
            for (int i = 0; i < 6; i++) {
                int gate = w_c24[i] >> 3, cc = w_c24[i] & 7;
                rw[i] = Wh[(size_t)(k0 + w_kk[i]) * H3 + gate * HH + c0 + cc];
            }
        }
        // compute: 64 k-values, 4 at a time
#pragma unroll
        for (int kk = 0; kk < 64; kk += 4) {
            float4 hv = *(const float4*)&h_s[b][kk];
            float4 w0 = *(const float4*)&w_s[c][kk];
            float4 w1 = *(const float4*)&w_s[8 + c][kk];
            float4 w2 = *(const float4*)&w_s[16 + c][kk];
            a0 += hv.x*w0.x + hv.y*w0.y + hv.z*w0.z + hv.w*w0.w;
            a1 += hv.x*w1.x + hv.y*w1.y + hv.z*w1.z + hv.w*w1.w;
            a2 += hv.x*w2.x + hv.y*w2.y + hv.z*w2.z + hv.w*w2.w;
        }
        __syncthreads();
        if (tile + 1 < 16) {
            *(float4*)&h_s[h_row0][h_q0 * 4] = rh0;
            *(float4*)&h_s[h_row1][h_q1 * 4] = rh1;
#pragma unroll
            for (int i = 0; i < 6; i++) w_s[w_c24[i]][w_kk[i]] = rw[i];
        }
    }

    const int col = c0 + c;
    const float* xzp = xz_base + (size_t)b * xz_rs;
    float z  = sigmoidf_(xzp[col] + a0);
    float r  = sigmoidf_(xzp[HH + col] + a1);
    float hh = tanhf(xzp[2 * HH + col] + r * a2);
    float hp = hprev ? hprev[(size_t)b * h_rs + col] : 0.0f;
    hout[(size_t)b * out_rs + col] = z * hp + (1.0f - z) * hh;
}

// ---------------------------------------------------------------------------
// Attention scores + softmax over encoder positions.
// One block per (b,d). scores[e] = Vb + sum_k tanh(w1e[b,e,k]+w2d[b,d,k])*Vw[k]
// ---------------------------------------------------------------------------
__global__ void attn_scores_kernel(const float* __restrict__ w1e,
                                   const float* __restrict__ w2d,
                                   const float* __restrict__ Vw,
                                   const float* __restrict__ Vb,
                                   float* __restrict__ attn)
{
    __shared__ float w2s[HH];
    __shared__ float vws[HH];
    __shared__ float ss[TT];

    const int bd = blockIdx.x;          // b*63 + d
    const int b  = bd / DD;
    const int t  = threadIdx.x;

    for (int k = t; k < HH; k += 256) {
        w2s[k] = w2d[(size_t)bd * HH + k];
        vws[k] = Vw[k];
    }
    __syncthreads();

    const int wid = t >> 5, lane = t & 31;
    for (int e = wid; e < TT; e += 8) {
        const float* w1p = w1e + ((size_t)b * TT + e) * HH;
        float acc = 0.0f;
        for (int k = lane; k < HH; k += 32)
            acc += fast_tanh(w1p[k] + w2s[k]) * vws[k];
#pragma unroll
        for (int o = 16; o; o >>= 1) acc += __shfl_xor_sync(0xffffffffu, acc, o);
        if (lane == 0) ss[e] = acc + Vb[0];
    }
    __syncthreads();

    if (t < 32) {
        float v0 = ss[t], v1 = ss[t + 32];
        float m = fmaxf(v0, v1);
#pragma unroll
        for (int o = 16; o; o >>= 1) m = fmaxf(m, __shfl_xor_sync(0xffffffffu, m, o));
        float e0 = expf(v0 - m), e1 = expf(v1 - m);
        float s = e0 + e1;
#pragma unroll
        for (int o = 16; o; o >>= 1) s += __shfl_xor_sync(0xffffffffu, s, o);
        float inv = 1.0f / s;
        attn[(size_t)bd * TT + t]      = e0 * inv;
        attn[(size_t)bd * TT + t + 32] = e1 * inv;
    }
}

// ---------------------------------------------------------------------------
// context = attn @ enc_out, attention_vector = tanh([context, dec_out]).
// One block per (b,d), 256 threads, 4 h each (float4 path).
// ---------------------------------------------------------------------------
__global__ void context_av_kernel(const float* __restrict__ attn,
                                  const float* __restrict__ enc_out,
                                  const float* __restrict__ dec_out,
                                  float* __restrict__ av)
{
    __shared__ float as[TT];
    const int bd = blockIdx.x;
    const int b  = bd / DD;
    const int t  = threadIdx.x;

    if (t < TT) as[t] = attn[(size_t)bd * TT + t];
    __syncthreads();

    const int h0 = t * 4;
    float ax = 0, ay = 0, az = 0, aw = 0;
#pragma unroll 4
    for (int e = 0; e < TT; e++) {
        float a = as[e];
        float4 v = *(const float4*)(enc_out + ((size_t)b * TT + e) * HH + h0);
        ax += a * v.x; ay += a * v.y; az += a * v.z; aw += a * v.w;
    }
    float* avp = av + (size_t)bd * (2 * HH);
    avp[h0 + 0] = tanhf(ax);
    avp[h0 + 1] = tanhf(ay);
    avp[h0 + 2] = tanhf(az);
    avp[h0 + 3] = tanhf(aw);

    float4 dv = *(const float4*)(dec_out + (size_t)bd * HH + h0);
    avp[HH + h0 + 0] = tanhf(dv.x);
    avp[HH + h0 + 1] = tanhf(dv.y);
    avp[HH + h0 + 2] = tanhf(dv.z);
    avp[HH + h0 + 3] = tanhf(dv.w);
}

// ---------------------------------------------------------------------------
// Host launcher
// ---------------------------------------------------------------------------
extern "C" void kernel_launch(void* const* d_in, const int* in_sizes, int n_in,
                              void* d_out, int out_size)
{
    const int*   input_ids  = (const int*)  d_in[0];
    const int*   target_ids = (const int*)  d_in[1];
    const float* emb_enc    = (const float*)d_in[2];
    const float* emb_dec    = (const float*)d_in[3];
    const float* enc_Wx     = (const float*)d_in[4];
    const float* enc_Wh     = (const float*)d_in[5];
    const float* enc_b      = (const float*)d_in[6];
    const float* dec_Wx     = (const float*)d_in[7];
    const float* dec_Wh     = (const float*)d_in[8];
    const float* dec_b      = (const float*)d_in[9];
    const float* W1         = (const float*)d_in[10];
    const float* W2         = (const float*)d_in[11];
    const float* V_w        = (const float*)d_in[12];
    const float* V_b        = (const float*)d_in[13];
    const float* Wp         = (const float*)d_in[14];
    const float* bp         = (const float*)d_in[15];
    float* out = (float*)d_out;

    float *xz_enc, *xz_dec, *enc_out, *dec_out, *w1e, *w2d, *attn, *av;
    cudaGetSymbolAddress((void**)&xz_enc,  g_xz_enc);
    cudaGetSymbolAddress((void**)&xz_dec,  g_xz_dec);
    cudaGetSymbolAddress((void**)&enc_out, g_enc_out);
    cudaGetSymbolAddress((void**)&dec_out, g_dec_out);
    cudaGetSymbolAddress((void**)&w1e,     g_w1e);
    cudaGetSymbolAddress((void**)&w2d,     g_w2d);
    cudaGetSymbolAddress((void**)&attn,    g_attn);
    cudaGetSymbolAddress((void**)&av,      g_av);

    // 1) xz = emb[ids] @ Wx + b  (encoder: M=2048, decoder: M=2016), N=3072, K=256
    {
        dim3 grid(H3 / 64, (BB * TT + 127) / 128);
        sgemm128<<<grid, 256>>>(nullptr, enc_Wx, enc_b, xz_enc,
                                BB * TT, H3, EE, input_ids, TT, emb_enc);
    }
    {
        dim3 grid(H3 / 64, (BB * DD + 127) / 128);
        sgemm128<<<grid, 256>>>(nullptr, dec_Wx, dec_b, xz_dec,
                                BB * DD, H3, EE, target_ids, DD, emb_dec);
    }

    // 2) Encoder GRU: 64 sequential steps. h_t written into enc_out[:, t, :].
    for (int t = 0; t < TT; t++) {
        const float* hprev = (t == 0) ? nullptr : (enc_out + (size_t)(t - 1) * HH);
        gru_step_kernel<<<128, 256>>>(xz_enc + (size_t)t * H3, TT * H3,
                                      hprev, TT * HH,
                                      enc_Wh,
                                      enc_out + (size_t)t * HH, TT * HH);
    }

    // 3) Decoder GRU: 63 steps, h0 = enc_out[:, 63, :]
    for (int t = 0; t < DD; t++) {
        const float* hprev;
        int h_rs;
        if (t == 0) { hprev = enc_out + (size_t)(TT - 1) * HH; h_rs = TT * HH; }
        else        { hprev = dec_out + (size_t)(t - 1) * HH;  h_rs = DD * HH; }
        gru_step_kernel<<<128, 256>>>(xz_dec + (size_t)t * H3, DD * H3,
                                      hprev, h_rs,
                                      dec_Wh,
                                      dec_out + (size_t)t * HH, DD * HH);
    }

    // 4) w1e = enc_out @ W1, w2d = dec_out @ W2
    {
        dim3 grid(HH / 64, (BB * TT + 127) / 128);
        sgemm128<<<grid, 256>>>(enc_out, W1, nullptr, w1e,
                                BB * TT, HH, HH, nullptr, 0, nullptr);
    }
    {
        dim3 grid(HH / 64, (BB * DD + 127) / 128);
        sgemm128<<<grid, 256>>>(dec_out, W2, nullptr, w2d,
                                BB * DD, HH, HH, nullptr, 0, nullptr);
    }

    // 5) attention scores + softmax
    attn_scores_kernel<<<BB * DD, 256>>>(w1e, w2d, V_w, V_b, attn);

    // 6) context + attention vector
    context_av_kernel<<<BB * DD, 256>>>(attn, enc_out, dec_out, av);

    // 7) logits = av @ Wp + bp  (M=2016, N=16000, K=2048)
    {
        dim3 grid(VV / 64, (BB * DD + 127) / 128);
        sgemm128<<<grid, 256>>>(av, Wp, bp, out,
                                BB * DD, VV, 2 * HH, nullptr, 0, nullptr);
    }
    (void)in_sizes; (void)n_in; (void)out_size;
}

// round 6
// speedup vs baseline: 1.7430x; 1.0404x over previous
#include <cuda_runtime.h>
#include <cuda_bf16.h>
#include <math.h>

// Problem constants
#define BB   32
#define TT   64
#define DD   63
#define EE   256
#define HH   1024
#define H3   3072
#define VV   16000

// ---------------------------------------------------------------------------
// Scratch (device globals; no runtime allocation allowed)
// ---------------------------------------------------------------------------
__device__ float g_xz_enc[BB * TT * H3];   // [B,T,3H]
__device__ float g_xz_dec[BB * DD * H3];   // [B,D,3H]
__device__ float g_enc_out[BB * TT * HH];  // [B,T,H]
__device__ float g_dec_out[BB * DD * HH];  // [B,D,H]
__device__ float g_w1e[BB * TT * HH];      // [B,T,H]
__device__ float g_w2d[BB * DD * HH];      // [B,D,H]
__device__ float g_attn[BB * DD * TT];     // [B,D,T]
__device__ float g_av[BB * DD * 2 * HH];   // [B,D,2H]

__device__ __forceinline__ float sigmoidf_(float x) { return 1.0f / (1.0f + expf(-x)); }

__device__ __forceinline__ float fast_tanh(float x) {
    float y;
    asm("tanh.approx.f32 %0, %1;" : "=f"(y) : "f"(x));
    return y;
}

// ---------------------------------------------------------------------------
// Tiled SGEMM v2: C[M,N] = gatherA(M,K) @ Bm[K,N] (+ bias[n])
// BM=128, BN=64, BK=16, 256 threads, 8x4 microtile, float4 smem traffic,
// software-pipelined global staging. N % 64 == 0, K % 16 == 0.
// If ids != nullptr: A row m comes from emb[ids[(m/seqlen)*64 + m%seqlen], :K].
// ---------------------------------------------------------------------------
__global__ __launch_bounds__(256) void sgemm128(
        const float* __restrict__ A,
        const float* __restrict__ Bm,
        const float* __restrict__ bias,
        float* __restrict__ C,
        int M, int N, int K,
        const int* __restrict__ ids, int seqlen,
        const float* __restrict__ emb)
{
    __shared__ float As[16][132];   // [k][m], 132-pad keeps rows 16B-aligned
    __shared__ float Bs[16][64];    // [k][n]

    const int bm = blockIdx.y * 128;
    const int bn = blockIdx.x * 64;
    const int t  = threadIdx.x;     // 0..255
    const int tx = t & 15;          // N dir (4 cols)
    const int ty = t >> 4;          // M dir (8 rows)

    // staging maps
    const int a_ml0 = (t) >> 2;            // i=0
    const int a_q0  = (t) & 3;
    const int a_ml1 = (t + 256) >> 2;      // i=1
    const int a_q1  = (t + 256) & 3;
    const int b_kk  = t >> 4;
    const int b_n4  = t & 15;

    float acc[8][4];
#pragma unroll
    for (int i = 0; i < 8; i++)
#pragma unroll
        for (int j = 0; j < 4; j++) acc[i][j] = 0.0f;

    // resolve A row pointers for the two staged rows (gather or direct)
    const float* arow0 = nullptr;
    const float* arow1 = nullptr;
    {
        int m0 = bm + a_ml0, m1 = bm + a_ml1;
        if (m0 < M) {
            if (ids) { int b = m0 / seqlen, tt2 = m0 - b * seqlen;
                       arow0 = emb + (size_t)ids[b * 64 + tt2] * K; }
            else       arow0 = A + (size_t)m0 * K;
        }
        if (m1 < M) {
            if (ids) { int b = m1 / seqlen, tt2 = m1 - b * seqlen;
                       arow1 = emb + (size_t)ids[b * 64 + tt2] * K; }
            else       arow1 = A + (size_t)m1 * K;
        }
    }

    const int ntiles = K >> 4;
    float4 ra0, ra1, rb;

    // prologue: load tile 0
    ra0 = arow0 ? *(const float4*)(arow0 + a_q0 * 4) : make_float4(0.f,0.f,0.f,0.f);
    ra1 = arow1 ? *(const float4*)(arow1 + a_q1 * 4) : make_float4(0.f,0.f,0.f,0.f);
    rb  = *(const float4*)(Bm + (size_t)b_kk * N + bn + b_n4 * 4);
    // store tile 0 to smem
    As[a_q0*4+0][a_ml0] = ra0.x; As[a_q0*4+1][a_ml0] = ra0.y;
    As[a_q0*4+2][a_ml0] = ra0.z; As[a_q0*4+3][a_ml0] = ra0.w;
    As[a_q1*4+0][a_ml1] = ra1.x; As[a_q1*4+1][a_ml1] = ra1.y;
    As[a_q1*4+2][a_ml1] = ra1.z; As[a_q1*4+3][a_ml1] = ra1.w;
    *(float4*)&Bs[b_kk][b_n4*4] = rb;

    for (int tile = 0; tile < ntiles; tile++) {
        __syncthreads();
        // prefetch next tile into registers
        if (tile + 1 < ntiles) {
            int k0 = (tile + 1) << 4;
            ra0 = arow0 ? *(const float4*)(arow0 + k0 + a_q0 * 4) : make_float4(0.f,0.f,0.f,0.f);
            ra1 = arow1 ? *(const float4*)(arow1 + k0 + a_q1 * 4) : make_float4(0.f,0.f,0.f,0.f);
            rb  = *(const float4*)(Bm + (size_t)(k0 + b_kk) * N + bn + b_n4 * 4);
        }
        // compute current tile
#pragma unroll
        for (int kk = 0; kk < 16; kk++) {
            float4 a0 = *(const float4*)&As[kk][ty * 8];
            float4 a1 = *(const float4*)&As[kk][ty * 8 + 4];
            float4 b0 = *(const float4*)&Bs[kk][tx * 4];
            acc[0][0] += a0.x*b0.x; acc[0][1] += a0.x*b0.y; acc[0][2] += a0.x*b0.z; acc[0][3] += a0.x*b0.w;
            acc[1][0] += a0.y*b0.x; acc[1][1] += a0.y*b0.y; acc[1][2] += a0.y*b0.z; acc[1][3] += a0.y*b0.w;
            acc[2][0] += a0.z*b0.x; acc[2][1] += a0.z*b0.y; acc[2][2] += a0.z*b0.z; acc[2][3] += a0.z*b0.w;
            acc[3][0] += a0.w*b0.x; acc[3][1] += a0.w*b0.y; acc[3][2] += a0.w*b0.z; acc[3][3] += a0.w*b0.w;
            acc[4][0] += a1.x*b0.x; acc[4][1] += a1.x*b0.y; acc[4][2] += a1.x*b0.z; acc[4][3] += a1.x*b0.w;
            acc[5][0] += a1.y*b0.x; acc[5][1] += a1.y*b0.y; acc[5][2] += a1.y*b0.z; acc[5][3] += a1.y*b0.w;
            acc[6][0] += a1.z*b0.x; acc[6][1] += a1.z*b0.y; acc[6][2] += a1.z*b0.z; acc[6][3] += a1.z*b0.w;
            acc[7][0] += a1.w*b0.x; acc[7][1] += a1.w*b0.y; acc[7][2] += a1.w*b0.z; acc[7][3] += a1.w*b0.w;
        }
        __syncthreads();
        if (tile + 1 < ntiles) {
            As[a_q0*4+0][a_ml0] = ra0.x; As[a_q0*4+1][a_ml0] = ra0.y;
            As[a_q0*4+2][a_ml0] = ra0.z; As[a_q0*4+3][a_ml0] = ra0.w;
            As[a_q1*4+0][a_ml1] = ra1.x; As[a_q1*4+1][a_ml1] = ra1.y;
            As[a_q1*4+2][a_ml1] = ra1.z; As[a_q1*4+3][a_ml1] = ra1.w;
            *(float4*)&Bs[b_kk][b_n4*4] = rb;
        }
    }

    // epilogue
    float4 bv = make_float4(0.f,0.f,0.f,0.f);
    if (bias) bv = *(const float4*)(bias + bn + tx * 4);
#pragma unroll
    for (int i = 0; i < 8; i++) {
        int m = bm + ty * 8 + i;
        if (m < M) {
            float4 o;
            o.x = acc[i][0] + bv.x; o.y = acc[i][1] + bv.y;
            o.z = acc[i][2] + bv.z; o.w = acc[i][3] + bv.w;
            *(float4*)(C + (size_t)m * N + bn + tx * 4) = o;
        }
    }
}

// ---------------------------------------------------------------------------
// One GRU time step v3: in-block k-split for latency hiding.
// grid = 128 blocks (8 h-cols = 24 gate-cols each), 1024 threads = 4 teams
// of 256. Team tm reduces k in [tm*256, tm*256+256) over 8 tiles of 32 k.
// Partials combined in smem; team 0 applies gates. hprev==nullptr -> h=0.
// ---------------------------------------------------------------------------
#define GTEAMS  4
#define GKT     256   // k per team
#define GTILE   32    // k per tile
#define GNT     8     // tiles per team

__global__ __launch_bounds__(1024) void gru_step_kernel(
        const float* __restrict__ xz_base, int xz_rs,
        const float* __restrict__ hprev, int h_rs,
        const float* __restrict__ Wh,
        float* __restrict__ hout, int out_rs)
{
    __shared__ float h_s[GTEAMS][32][36];   // [team][b][k] pad 36: conflict-free
    __shared__ float w_s[GTEAMS][24][36];   // [team][gate*8+c][k]
    __shared__ float red[GTEAMS][256][3];   // per-team partials

    const int t    = threadIdx.x;       // 0..1023
    const int team = t >> 8;            // 0..3
    const int tt   = t & 255;
    const int b    = tt & 31;
    const int c    = tt >> 5;           // 0..7
    const int c0   = blockIdx.x * 8;
    const int kbase = team * GKT;

    // h staging: 32 b x 32 k = 256 float4, one per thread
    const int h_row = tt >> 3;          // 0..31
    const int h_q   = tt & 7;           // float4 slot 0..7
    // w staging: 24 x 32 = 768 floats, 3 per thread
    int w_kk[3], w_c24[3];
#pragma unroll
    for (int i = 0; i < 3; i++) {
        int flat = tt + i * 256;        // 0..767
        w_kk[i]  = flat / 24;
        w_c24[i] = flat - w_kk[i] * 24;
    }

    float a0 = 0.0f, a1 = 0.0f, a2 = 0.0f;
    float4 rh;
    float  rw[3];

    // prologue: load tile 0 of this team's k-range
    if (hprev) rh = *(const float4*)(hprev + (size_t)h_row * h_rs + kbase + h_q * 4);
    else       rh = make_float4(0.f, 0.f, 0.f, 0.f);
#pragma unroll
    for (int i = 0; i < 3; i++) {
        int gate = w_c24[i] >> 3, cc = w_c24[i] & 7;
        rw[i] = Wh[(size_t)(kbase + w_kk[i]) * H3 + gate * HH + c0 + cc];
    }
    *(float4*)&h_s[team][h_row][h_q * 4] = rh;
#pragma unroll
    for (int i = 0; i < 3; i++) w_s[team][w_c24[i]][w_kk[i]] = rw[i];

    for (int tile = 0; tile < GNT; tile++) {
        __syncthreads();
        // prefetch next tile into registers
        if (tile + 1 < GNT) {
            int k0 = kbase + (tile + 1) * GTILE;
            if (hprev)
                rh = *(const float4*)(hprev + (size_t)h_row * h_rs + k0 + h_q * 4);
#pragma unroll
            for (int i = 0; i < 3; i++) {
                int gate = w_c24[i] >> 3, cc = w_c24[i] & 7;
                rw[i] = Wh[(size_t)(k0 + w_kk[i]) * H3 + gate * HH + c0 + cc];
            }
        }
        // compute current tile: 32 k, 4 at a time
#pragma unroll
        for (int kk = 0; kk < GTILE; kk += 4) {
            float4 hv = *(const float4*)&h_s[team][b][kk];
            float4 w0 = *(const float4*)&w_s[team][c][kk];
            float4 w1 = *(const float4*)&w_s[team][8 + c][kk];
            float4 w2 = *(const float4*)&w_s[team][16 + c][kk];
            a0 += hv.x*w0.x + hv.y*w0.y + hv.z*w0.z + hv.w*w0.w;
            a1 += hv.x*w1.x + hv.y*w1.y + hv.z*w1.z + hv.w*w1.w;
            a2 += hv.x*w2.x + hv.y*w2.y + hv.z*w2.z + hv.w*w2.w;
        }
        __syncthreads();
        if (tile + 1 < GNT) {
            *(float4*)&h_s[team][h_row][h_q * 4] = rh;
#pragma unroll
            for (int i = 0; i < 3; i++) w_s[team][w_c24[i]][w_kk[i]] = rw[i];
        }
    }

    // cross-team reduction
    red[team][tt][0] = a0;
    red[team][tt][1] = a1;
    red[team][tt][2] = a2;
    __syncthreads();

    if (team == 0) {
        float s0 = red[0][tt][0] + red[1][tt][0] + red[2][tt][0] + red[3][tt][0];
        float s1 = red[0][tt][1] + red[1][tt][1] + red[2][tt][1] + red[3][tt][1];
        float s2 = red[0][tt][2] + red[1][tt][2] + red[2][tt][2] + red[3][tt][2];

        const int col = c0 + c;
        const float* xzp = xz_base + (size_t)b * xz_rs;
        float z  = sigmoidf_(xzp[col] + s0);
        float r  = sigmoidf_(xzp[HH + col] + s1);
        float hh = tanhf(xzp[2 * HH + col] + r * s2);
        float hp = hprev ? hprev[(size_t)b * h_rs + col] : 0.0f;
        hout[(size_t)b * out_rs + col] = z * hp + (1.0f - z) * hh;
    }
}

// ---------------------------------------------------------------------------
// Attention scores + softmax over encoder positions.
// One block per (b,d). scores[e] = Vb + sum_k tanh(w1e[b,e,k]+w2d[b,d,k])*Vw[k]
// ---------------------------------------------------------------------------
__global__ void attn_scores_kernel(const float* __restrict__ w1e,
                                   const float* __restrict__ w2d,
                                   const float* __restrict__ Vw,
                                   const float* __restrict__ Vb,
                                   float* __restrict__ attn)
{
    __shared__ float w2s[HH];
    __shared__ float vws[HH];
    __shared__ float ss[TT];

    const int bd = blockIdx.x;          // b*63 + d
    const int b  = bd / DD;
    const int t  = threadIdx.x;

    for (int k = t; k < HH; k += 256) {
        w2s[k] = w2d[(size_t)bd * HH + k];
        vws[k] = Vw[k];
    }
    __syncthreads();

    const int wid = t >> 5, lane = t & 31;
    for (int e = wid; e < TT; e += 8) {
        const float* w1p = w1e + ((size_t)b * TT + e) * HH;
        float acc = 0.0f;
        for (int k = lane; k < HH; k += 32)
            acc += fast_tanh(w1p[k] + w2s[k]) * vws[k];
#pragma unroll
        for (int o = 16; o; o >>= 1) acc += __shfl_xor_sync(0xffffffffu, acc, o);
        if (lane == 0) ss[e] = acc + Vb[0];
    }
    __syncthreads();

    if (t < 32) {
        float v0 = ss[t], v1 = ss[t + 32];
        float m = fmaxf(v0, v1);
#pragma unroll
        for (int o = 16; o; o >>= 1) m = fmaxf(m, __shfl_xor_sync(0xffffffffu, m, o));
        float e0 = expf(v0 - m), e1 = expf(v1 - m);
        float s = e0 + e1;
#pragma unroll
        for (int o = 16; o; o >>= 1) s += __shfl_xor_sync(0xffffffffu, s, o);
        float inv = 1.0f / s;
        attn[(size_t)bd * TT + t]      = e0 * inv;
        attn[(size_t)bd * TT + t + 32] = e1 * inv;
    }
}

// ---------------------------------------------------------------------------
// context = attn @ enc_out, attention_vector = tanh([context, dec_out]).
// One block per (b,d), 256 threads, 4 h each (float4 path).
// ---------------------------------------------------------------------------
__global__ void context_av_kernel(const float* __restrict__ attn,
                                  const float* __restrict__ enc_out,
                                  const float* __restrict__ dec_out,
                                  float* __restrict__ av)
{
    __shared__ float as[TT];
    const int bd = blockIdx.x;
    const int b  = bd / DD;
    const int t  = threadIdx.x;

    if (t < TT) as[t] = attn[(size_t)bd * TT + t];
    __syncthreads();

    const int h0 = t * 4;
    float ax = 0, ay = 0, az = 0, aw = 0;
#pragma unroll 4
    for (int e = 0; e < TT; e++) {
        float a = as[e];
        float4 v = *(const float4*)(enc_out + ((size_t)b * TT + e) * HH + h0);
        ax += a * v.x; ay += a * v.y; az += a * v.z; aw += a * v.w;
    }
    float* avp = av + (size_t)bd * (2 * HH);
    avp[h0 + 0] = tanhf(ax);
    avp[h0 + 1] = tanhf(ay);
    avp[h0 + 2] = tanhf(az);
    avp[h0 + 3] = tanhf(aw);

    float4 dv = *(const float4*)(dec_out + (size_t)bd * HH + h0);
    avp[HH + h0 + 0] = tanhf(dv.x);
    avp[HH + h0 + 1] = tanhf(dv.y);
    avp[HH + h0 + 2] = tanhf(dv.z);
    avp[HH + h0 + 3] = tanhf(dv.w);
}

// ---------------------------------------------------------------------------
// Host launcher
// ---------------------------------------------------------------------------
extern "C" void kernel_launch(void* const* d_in, const int* in_sizes, int n_in,
                              void* d_out, int out_size)
{
    const int*   input_ids  = (const int*)  d_in[0];
    const int*   target_ids = (const int*)  d_in[1];
    const float* emb_enc    = (const float*)d_in[2];
    const float* emb_dec    = (const float*)d_in[3];
    const float* enc_Wx     = (const float*)d_in[4];
    const float* enc_Wh     = (const float*)d_in[5];
    const float* enc_b      = (const float*)d_in[6];
    const float* dec_Wx     = (const float*)d_in[7];
    const float* dec_Wh     = (const float*)d_in[8];
    const float* dec_b      = (const float*)d_in[9];
    const float* W1         = (const float*)d_in[10];
    const float* W2         = (const float*)d_in[11];
    const float* V_w        = (const float*)d_in[12];
    const float* V_b        = (const float*)d_in[13];
    const float* Wp         = (const float*)d_in[14];
    const float* bp         = (const float*)d_in[15];
    float* out = (float*)d_out;

    float *xz_enc, *xz_dec, *enc_out, *dec_out, *w1e, *w2d, *attn, *av;
    cudaGetSymbolAddress((void**)&xz_enc,  g_xz_enc);
    cudaGetSymbolAddress((void**)&xz_dec,  g_xz_dec);
    cudaGetSymbolAddress((void**)&enc_out, g_enc_out);
    cudaGetSymbolAddress((void**)&dec_out, g_dec_out);
    cudaGetSymbolAddress((void**)&w1e,     g_w1e);
    cudaGetSymbolAddress((void**)&w2d,     g_w2d);
    cudaGetSymbolAddress((void**)&attn,    g_attn);
    cudaGetSymbolAddress((void**)&av,      g_av);

    // 1) xz = emb[ids] @ Wx + b  (encoder: M=2048, decoder: M=2016), N=3072, K=256
    {
        dim3 grid(H3 / 64, (BB * TT + 127) / 128);
        sgemm128<<<grid, 256>>>(nullptr, enc_Wx, enc_b, xz_enc,
                                BB * TT, H3, EE, input_ids, TT, emb_enc);
    }
    {
        dim3 grid(H3 / 64, (BB * DD + 127) / 128);
        sgemm128<<<grid, 256>>>(nullptr, dec_Wx, dec_b, xz_dec,
                                BB * DD, H3, EE, target_ids, DD, emb_dec);
    }

    // 2) Encoder GRU: 64 sequential steps. h_t written into enc_out[:, t, :].
    for (int t = 0; t < TT; t++) {
        const float* hprev = (t == 0) ? nullptr : (enc_out + (size_t)(t - 1) * HH);
        gru_step_kernel<<<128, 1024>>>(xz_enc + (size_t)t * H3, TT * H3,
                                       hprev, TT * HH,
                                       enc_Wh,
                                       enc_out + (size_t)t * HH, TT * HH);
    }

    // 3) Decoder GRU: 63 steps, h0 = enc_out[:, 63, :]
    for (int t = 0; t < DD; t++) {
        const float* hprev;
        int h_rs;
        if (t == 0) { hprev = enc_out + (size_t)(TT - 1) * HH; h_rs = TT * HH; }
        else        { hprev = dec_out + (size_t)(t - 1) * HH;  h_rs = DD * HH; }
        gru_step_kernel<<<128, 1024>>>(xz_dec + (size_t)t * H3, DD * H3,
                                       hprev, h_rs,
                                       dec_Wh,
                                       dec_out + (size_t)t * HH, DD * HH);
    }

    // 4) w1e = enc_out @ W1, w2d = dec_out @ W2
    {
        dim3 grid(HH / 64, (BB * TT + 127) / 128);
        sgemm128<<<grid, 256>>>(enc_out, W1, nullptr, w1e,
                                BB * TT, HH, HH, nullptr, 0, nullptr);
    }
    {
        dim3 grid(HH / 64, (BB * DD + 127) / 128);
        sgemm128<<<grid, 256>>>(dec_out, W2, nullptr, w2d,
                                BB * DD, HH, HH, nullptr, 0, nullptr);
    }

    // 5) attention scores + softmax
    attn_scores_kernel<<<BB * DD, 256>>>(w1e, w2d, V_w, V_b, attn);

    // 6) context + attention vector
    context_av_kernel<<<BB * DD, 256>>>(attn, enc_out, dec_out, av);

    // 7) logits = av @ Wp + bp  (M=2016, N=16000, K=2048)
    {
        dim3 grid(VV / 64, (BB * DD + 127) / 128);
        sgemm128<<<grid, 256>>>(av, Wp, bp, out,
                                BB * DD, VV, 2 * HH, nullptr, 0, nullptr);
    }
    (void)in_sizes; (void)n_in; (void)out_size;
}